// round 15
// baseline (speedup 1.0000x reference)
#include <cuda_runtime.h>
#include <cuda_bf16.h>
#include <math.h>
#include <stdint.h>

#define H 128
#define IN_C 32
#define N_IP 20000
#define N_PP 50000
#define N_FL 100000
#define E_CNT 200000
#define N_ITER 4
#define N_NODES 220000

// message/node-space ordering: [ip | pp_fl | fl | pp_ip]
#define G_IP    0
#define G_PPFL  20000
#define G_FL    70000
#define G_PPIP  170000
// h ordering: [ip | pp | fl]
#define HB_IP   0
#define HB_PP   20000
#define HB_FL   70000
#define HB_ROWS 170000

typedef __nv_bfloat16 bf;

// ---------------------------------------------------------------------------
// Scratch
// ---------------------------------------------------------------------------
static constexpr size_t B_HB      = 0;                                  // bf16 h, 170000 x 128
static constexpr size_t B_PROJ_IP = B_HB      + (size_t)HB_ROWS * H;    // [Ws_ip|Wd_ip] ld 256
static constexpr size_t B_PROJ_PP = B_PROJ_IP + (size_t)N_IP * 2 * H;   // ld 512
static constexpr size_t B_PROJ_FL = B_PROJ_PP + (size_t)N_PP * 4 * H;   // ld 256
static constexpr size_t B_G       = B_PROJ_FL + (size_t)N_FL * 2 * H;   // gates [rz|gin|ghn] 170000 x 512
static constexpr size_t B_G2      = B_G       + (size_t)HB_ROWS * 512;  // 50000 x 512
static constexpr size_t B_R1      = B_G2      + (size_t)N_PP * 512;
static constexpr size_t B_R2      = B_R1      + (size_t)N_FL * H;
static constexpr size_t B_WB      = B_R2      + (size_t)N_FL * 64;
static constexpr size_t WB_MSG    = 0;                                  // [512][128]
static constexpr size_t WB_IH_IP  = WB_MSG    + 65536;
static constexpr size_t WB_HH_IP  = WB_IH_IP  + 49152;
static constexpr size_t WB_IH_FL  = WB_HH_IP  + 49152;
static constexpr size_t WB_HH_FL  = WB_IH_FL  + 49152;
static constexpr size_t WB_W1     = WB_HH_FL  + 49152;
static constexpr size_t WB_W2     = WB_W1     + 16384;
static constexpr size_t WB_TOTAL  = WB_W2     + 8192;                   // 295936 (even)
static constexpr size_t B_TOTAL   = B_WB + WB_TOTAL;
__device__ bf d_b16[B_TOTAL];

// fp8 regions (bytes)
static constexpr size_t Q_HQ    = 0;                                    // 170000 x 128
static constexpr size_t Q_MQ    = Q_HQ + (size_t)HB_ROWS * H;           // 220000 x 128
static constexpr size_t Q_WQ    = Q_MQ + (size_t)N_NODES * H;
static constexpr size_t Q_TOTAL = Q_WQ + WB_TOTAL;
__device__ uint8_t d_fp8[Q_TOTAL];

__device__ float d_bias[512];   // [0:256) = b_ih_ip+b_hh_ip, [256:512) = b_ih_fl+b_hh_fl

__device__ int d_cnt[N_NODES];
__device__ int d_cursor[N_NODES];
__device__ int d_rowptr[N_NODES + 1];
__device__ int d_elist[4 * E_CNT];

#define SC_T 512
#define SC_I 4
#define SC_C (SC_T * SC_I)
#define SC_NB ((N_NODES + SC_C - 1) / SC_C)
__device__ int d_bsum[128];
__device__ int d_boff[128];

// ---------------------------------------------------------------------------
// asm helpers
// ---------------------------------------------------------------------------
#define CPA16(dst, src, sz) \
    asm volatile("cp.async.cg.shared.global [%0], [%1], 16, %2;" \
                 :: "r"(dst), "l"(src), "r"(sz))

#define LDSM4(r0, r1, r2, r3, addr) \
    asm volatile("ldmatrix.sync.aligned.m8n8.x4.shared.b16 {%0,%1,%2,%3}, [%4];" \
                 : "=r"(r0), "=r"(r1), "=r"(r2), "=r"(r3) : "r"(addr))

#define MMA_BF16(d, a, b) \
    asm volatile("mma.sync.aligned.m16n8k16.row.col.f32.bf16.bf16.f32 " \
        "{%0,%1,%2,%3}, {%4,%5,%6,%7}, {%8,%9}, {%0,%1,%2,%3};" \
        : "+f"((d)[0]), "+f"((d)[1]), "+f"((d)[2]), "+f"((d)[3]) \
        : "r"((a)[0]), "r"((a)[1]), "r"((a)[2]), "r"((a)[3]), \
          "r"((b)[0]), "r"((b)[1]))

#define MMA_FP8(d, a, b) \
    asm volatile("mma.sync.aligned.m16n8k32.row.col.f32.e4m3.e4m3.f32 " \
        "{%0,%1,%2,%3}, {%4,%5,%6,%7}, {%8,%9}, {%0,%1,%2,%3};" \
        : "+f"((d)[0]), "+f"((d)[1]), "+f"((d)[2]), "+f"((d)[3]) \
        : "r"((a)[0]), "r"((a)[1]), "r"((a)[2]), "r"((a)[3]), \
          "r"((b)[0]), "r"((b)[1]))

__device__ __forceinline__ uint32_t scvta(const void* p) {
    return (uint32_t)__cvta_generic_to_shared(p);
}
__device__ __forceinline__ uint16_t pk2(float lo, float hi) {
    uint16_t r;
    asm("cvt.rn.satfinite.e4m3x2.f32 %0, %1, %2;" : "=h"(r) : "f"(hi), "f"(lo));
    return r;
}

// ---------------------------------------------------------------------------
// Job table (up to 6 jobs, 1-D grid over tiles).
// A2/W2 non-null => K=256 split mode: k[0:128) from A/W, k[128:256) from A2/W2.
// ---------------------------------------------------------------------------
struct Job {
    const void* A; const void* W; const void* A2; const void* W2;
    const float* bias; bf* C;
    int M, N, ldc, cofs, relu, tile_start, nx, pad;
};
struct Jobs { Job j[6]; int njobs; };

__device__ __forceinline__ int job_select(const Jobs& js, int t) {
    int ji = 0;
#pragma unroll
    for (int k = 1; k < 6; ++k)
        if (js.njobs > k && t >= js.j[k].tile_start) ji = k;
    return ji;
}

// ---------------------------------------------------------------------------
// FP8 mma GEMM: C[m, cofs+n] = sum_k A[m,k]*W[n*128+k] (+bias)(+relu), bf16 out
// Tile 128m x 64n, 8 warps (4m x 2n), acc 32 regs/thread -> 4 CTAs/SM.
// K=128 in 2 stages (K64 each); K=256 via A2/W2 ping-pong.
// ---------------------------------------------------------------------------
__global__ void __launch_bounds__(256, 4)
bgemm8(Jobs js)
{
    const int t = blockIdx.x;
    const Job J = js.j[job_select(js, t)];
    const int lt = t - J.tile_start;
    const int bn = (lt % J.nx) * 64;
    const int bm = (lt / J.nx) * 128;

    __shared__ __align__(16) uint16_t As[2][128][40];
    __shared__ __align__(16) uint16_t Bs[2][64][40];

    const int tid  = threadIdx.x;
    const int wid  = tid >> 5;
    const int lane = tid & 31;
    const int g    = lane >> 2;
    const int t4   = lane & 3;
    const int wm   = (wid >> 1) * 32;    // 4 m-groups of 32 rows
    const int wn   = (wid & 1) * 32;     // 2 n-groups of 32 cols

    const int lr  = tid >> 1;            // A row 0..127
    const int ha  = tid & 1;             // 32B half of A's 64B stage chunk
    const int rb  = tid >> 2;            // B row 0..63
    const int hb4 = tid & 3;             // 16B quarter of B's 64B stage chunk

    int arow = bm + lr;
    const uint32_t asz = (arow < J.M) ? 16u : 0u;
    if (arow >= J.M) arow = J.M - 1;
    const uint8_t* ap = (const uint8_t*)J.A + (size_t)arow * 128 + ha * 32;

    int brow = bn + rb;
    const uint32_t bsz = (brow < J.N) ? 16u : 0u;
    if (brow >= J.N) brow = J.N - 1;
    const uint8_t* bp = (const uint8_t*)J.W + (size_t)brow * 128 + hb4 * 16;

#define ISSUE8(buf, aptr, bptr)                                        \
    { uint32_t da = scvta(&As[buf][lr][ha * 16]);                      \
      uint32_t db = scvta(&Bs[buf][rb][hb4 * 8]);                      \
      CPA16(da, (aptr), asz); CPA16(da + 16, (aptr) + 16, asz);        \
      CPA16(db, (bptr), bsz);                                          \
      asm volatile("cp.async.commit_group;" ::: "memory"); }

    ISSUE8(0, ap, bp)
    ISSUE8(1, ap + 64, bp + 64)

    float acc[2][4][4];
#pragma unroll
    for (int i = 0; i < 2; ++i)
#pragma unroll
        for (int j = 0; j < 4; ++j)
#pragma unroll
            for (int k = 0; k < 4; ++k) acc[i][j][k] = 0.f;

#define COMPUTE8(s)                                                            \
    {                                                                          \
        _Pragma("unroll")                                                      \
        for (int kk = 0; kk < 2; ++kk) {                                       \
            uint32_t a[2][4];                                                  \
            _Pragma("unroll")                                                  \
            for (int mt = 0; mt < 2; ++mt) {                                   \
                uint32_t ad = scvta(&As[s][wm + mt * 16 + (lane & 15)]         \
                                        [kk * 16 + ((lane >> 4) << 3)]);       \
                LDSM4(a[mt][0], a[mt][1], a[mt][2], a[mt][3], ad);             \
            }                                                                  \
            uint32_t b[4][2];                                                  \
            _Pragma("unroll")                                                  \
            for (int p = 0; p < 2; ++p) {                                      \
                uint32_t ad = scvta(&Bs[s][wn + p * 16 + ((lane >> 4) & 1) * 8 \
                                           + (lane & 7)]                       \
                                        [kk * 16 + ((lane >> 3) & 1) * 8]);    \
                uint32_t r0, r1, r2, r3;                                       \
                LDSM4(r0, r1, r2, r3, ad);                                     \
                b[2 * p][0] = r0; b[2 * p][1] = r1;                            \
                b[2 * p + 1][0] = r2; b[2 * p + 1][1] = r3;                    \
            }                                                                  \
            _Pragma("unroll")                                                  \
            for (int mt = 0; mt < 2; ++mt)                                     \
                _Pragma("unroll")                                              \
                for (int nt = 0; nt < 4; ++nt)                                 \
                    MMA_FP8(acc[mt][nt], a[mt], b[nt]);                        \
        }                                                                      \
    }

#define WAITG(n) asm volatile("cp.async.wait_group " #n ";" ::: "memory")

    if (J.A2 == nullptr) {
        WAITG(1); __syncthreads(); COMPUTE8(0);
        WAITG(0); __syncthreads(); COMPUTE8(1);
    } else {
        const uint8_t* ap2 = (const uint8_t*)J.A2 + (size_t)arow * 128 + ha * 32;
        const uint8_t* bp2 = (const uint8_t*)J.W2 + (size_t)brow * 128 + hb4 * 16;
        WAITG(1); __syncthreads(); COMPUTE8(0); __syncthreads();
        ISSUE8(0, ap2, bp2)
        WAITG(1); __syncthreads(); COMPUTE8(1); __syncthreads();
        ISSUE8(1, ap2 + 64, bp2 + 64)
        WAITG(1); __syncthreads(); COMPUTE8(0);
        WAITG(0); __syncthreads(); COMPUTE8(1);
    }
#undef WAITG
#undef COMPUTE8
#undef ISSUE8

#pragma unroll
    for (int mt = 0; mt < 2; ++mt) {
#pragma unroll
        for (int hf = 0; hf < 2; ++hf) {
            int row = bm + wm + mt * 16 + g + hf * 8;
            if (row >= J.M) continue;
#pragma unroll
            for (int nt = 0; nt < 4; ++nt) {
                int col = bn + wn + nt * 8 + 2 * t4;
                if (col >= J.N) continue;
                float v0 = acc[mt][nt][hf * 2 + 0];
                float v1 = acc[mt][nt][hf * 2 + 1];
                if (J.bias) { v0 += J.bias[col]; v1 += J.bias[col + 1]; }
                if (J.relu) { v0 = fmaxf(v0, 0.f); v1 = fmaxf(v1, 0.f); }
                *(__nv_bfloat162*)(J.C + (size_t)row * J.ldc + J.cofs + col) =
                    __floats2bfloat162_rn(v0, v1);
            }
        }
    }
}

// ---------------------------------------------------------------------------
// bf16 mma GEMM (readout only; 128-wide tiles)
// ---------------------------------------------------------------------------
__global__ void __launch_bounds__(256, 2)
bgemm(Jobs js)
{
    const int t = blockIdx.x;
    const Job J = js.j[job_select(js, t)];
    const int lt = t - J.tile_start;
    const int bn = (lt % J.nx) * 128;
    const int bm = (lt / J.nx) * 128;

    extern __shared__ __align__(16) char dsm[];
    bf* As = (bf*)dsm;
    bf* Bs = (bf*)dsm + 4 * 5120;

    const int tid  = threadIdx.x;
    const int wid  = tid >> 5;
    const int lane = tid & 31;
    const int g    = lane >> 2;
    const int t4   = lane & 3;
    const int wm   = (wid & 1) * 64;
    const int wn   = (wid >> 1) * 32;

    const int lr = tid >> 1;
    const int kc = (tid & 1) * 16;

    int arow = bm + lr;
    const uint32_t asz = (arow < J.M) ? 16u : 0u;
    if (arow >= J.M) arow = J.M - 1;
    const bf* ap = (const bf*)J.A + (size_t)arow * 128 + kc;

    int brow = bn + lr;
    const uint32_t bsz = (brow < J.N) ? 16u : 0u;
    if (brow >= J.N) brow = J.N - 1;
    const bf* bp = (const bf*)J.W + (size_t)brow * 128 + kc;

#pragma unroll
    for (int st = 0; st < 4; ++st) {
        uint32_t da = scvta(As + st * 5120 + lr * 40 + kc);
        uint32_t db = scvta(Bs + st * 5120 + lr * 40 + kc);
        CPA16(da, ap + st * 32, asz); CPA16(da + 16, ap + st * 32 + 8, asz);
        CPA16(db, bp + st * 32, bsz); CPA16(db + 16, bp + st * 32 + 8, bsz);
        asm volatile("cp.async.commit_group;" ::: "memory");
    }

    float acc[4][4][4];
#pragma unroll
    for (int i = 0; i < 4; ++i)
#pragma unroll
        for (int j = 0; j < 4; ++j)
#pragma unroll
            for (int k = 0; k < 4; ++k) acc[i][j][k] = 0.f;

#define STAGE(s, WG)                                                           \
    {                                                                          \
        asm volatile("cp.async.wait_group " #WG ";" ::: "memory");             \
        __syncthreads();                                                       \
        const bf* as = As + (s) * 5120;                                        \
        const bf* bs_ = Bs + (s) * 5120;                                       \
        _Pragma("unroll")                                                      \
        for (int kk = 0; kk < 32; kk += 16) {                                  \
            uint32_t a[4][4];                                                  \
            _Pragma("unroll")                                                  \
            for (int mt = 0; mt < 4; ++mt) {                                   \
                uint32_t ad = scvta(as + (wm + mt * 16 + (lane & 15)) * 40     \
                                        + kk + ((lane >> 4) << 3));            \
                LDSM4(a[mt][0], a[mt][1], a[mt][2], a[mt][3], ad);             \
            }                                                                  \
            uint32_t b[4][2];                                                  \
            _Pragma("unroll")                                                  \
            for (int p = 0; p < 2; ++p) {                                      \
                int br = wn + p * 16 + ((lane >> 4) & 1) * 8 + (lane & 7);     \
                int bc = kk + ((lane >> 3) & 1) * 8;                           \
                uint32_t r0, r1, r2, r3;                                       \
                LDSM4(r0, r1, r2, r3, scvta(bs_ + br * 40 + bc));              \
                b[2 * p][0] = r0; b[2 * p][1] = r1;                            \
                b[2 * p + 1][0] = r2; b[2 * p + 1][1] = r3;                    \
            }                                                                  \
            _Pragma("unroll")                                                  \
            for (int mt = 0; mt < 4; ++mt)                                     \
                _Pragma("unroll")                                              \
                for (int nt = 0; nt < 4; ++nt)                                 \
                    MMA_BF16(acc[mt][nt], a[mt], b[nt]);                       \
        }                                                                      \
    }

    STAGE(0, 3)
    STAGE(1, 2)
    STAGE(2, 1)
    STAGE(3, 0)
#undef STAGE

#pragma unroll
    for (int mt = 0; mt < 4; ++mt) {
#pragma unroll
        for (int hf = 0; hf < 2; ++hf) {
            int row = bm + wm + mt * 16 + g + hf * 8;
            if (row >= J.M) continue;
#pragma unroll
            for (int nt = 0; nt < 4; ++nt) {
                int col = bn + wn + nt * 8 + 2 * t4;
                if (col >= J.N) continue;
                float v0 = acc[mt][nt][hf * 2 + 0];
                float v1 = acc[mt][nt][hf * 2 + 1];
                if (J.bias) { v0 += J.bias[col]; v1 += J.bias[col + 1]; }
                if (J.relu) { v0 = fmaxf(v0, 0.f); v1 = fmaxf(v1, 0.f); }
                *(__nv_bfloat162*)(J.C + (size_t)row * J.ldc + J.cofs + col) =
                    __floats2bfloat162_rn(v0, v1);
            }
        }
    }
}

// ---------------------------------------------------------------------------
// CSR build
// ---------------------------------------------------------------------------
__device__ __forceinline__ int seg_base(int set) {
    return (set == 0) ? G_PPIP : (set == 1) ? G_IP : (set == 2) ? G_FL : G_PPFL;
}

__global__ void edge_hist(const int* __restrict__ d0, const int* __restrict__ d1,
                          const int* __restrict__ d2, const int* __restrict__ d3,
                          int* __restrict__ cnt)
{
    int i = blockIdx.x * blockDim.x + threadIdx.x;
    if (i >= 4 * E_CNT) return;
    int set = i / E_CNT, e = i - set * E_CNT;
    const int* d = (set == 0) ? d0 : (set == 1) ? d1 : (set == 2) ? d2 : d3;
    atomicAdd(cnt + seg_base(set) + d[e], 1);
}

__global__ void scan_part(const int* __restrict__ cnt, int* __restrict__ bsum)
{
    __shared__ int sh[SC_T];
    int b = blockIdx.x, t = threadIdx.x;
    int base = b * SC_C + t * SC_I;
    int s = 0;
#pragma unroll
    for (int k = 0; k < SC_I; ++k) {
        int idx = base + k;
        if (idx < N_NODES) s += cnt[idx];
    }
    sh[t] = s;
    __syncthreads();
    for (int off = SC_T / 2; off > 0; off >>= 1) {
        if (t < off) sh[t] += sh[t + off];
        __syncthreads();
    }
    if (t == 0) bsum[b] = sh[0];
}

__global__ void scan_top(const int* __restrict__ bsum, int* __restrict__ boff)
{
    __shared__ int sh[128];
    int t = threadIdx.x;
    int v = (t < SC_NB) ? bsum[t] : 0;
    sh[t] = v;
    __syncthreads();
    for (int off = 1; off < 128; off <<= 1) {
        int u = (t >= off) ? sh[t - off] : 0;
        __syncthreads();
        sh[t] += u;
        __syncthreads();
    }
    if (t < SC_NB) boff[t] = sh[t] - v;
}

__global__ void scan_final(const int* __restrict__ cnt, const int* __restrict__ boff,
                           int* __restrict__ rowptr)
{
    __shared__ int sh[SC_T];
    int b = blockIdx.x, t = threadIdx.x;
    int base = b * SC_C + t * SC_I;
    int loc[SC_I];
    int s = 0;
#pragma unroll
    for (int k = 0; k < SC_I; ++k) {
        int idx = base + k;
        loc[k] = (idx < N_NODES) ? cnt[idx] : 0;
        s += loc[k];
    }
    sh[t] = s;
    __syncthreads();
    for (int off = 1; off < SC_T; off <<= 1) {
        int u = (t >= off) ? sh[t - off] : 0;
        __syncthreads();
        sh[t] += u;
        __syncthreads();
    }
    int run = boff[b] + sh[t] - s;
#pragma unroll
    for (int k = 0; k < SC_I; ++k) {
        int idx = base + k;
        if (idx < N_NODES) { rowptr[idx] = run; run += loc[k]; }
    }
    if (b == 0 && t == 0) rowptr[N_NODES] = 4 * E_CNT;
}

__global__ void edge_fill(const int* __restrict__ s0, const int* __restrict__ d0,
                          const int* __restrict__ s1, const int* __restrict__ d1,
                          const int* __restrict__ s2, const int* __restrict__ d2,
                          const int* __restrict__ s3, const int* __restrict__ d3,
                          const int* __restrict__ rowptr, int* __restrict__ cursor,
                          int* __restrict__ elist)
{
    int i = blockIdx.x * blockDim.x + threadIdx.x;
    if (i >= 4 * E_CNT) return;
    int set = i / E_CNT, e = i - set * E_CNT;
    const int *sp, *dp;
    switch (set) {
        case 0:  sp = s0; dp = d0; break;
        case 1:  sp = s1; dp = d1; break;
        case 2:  sp = s2; dp = d2; break;
        default: sp = s3; dp = d3; break;
    }
    int gidx = seg_base(set) + dp[e];
    int pos = atomicAdd(cursor + gidx, 1);
    elist[rowptr[gidx] + pos] = sp[e];
}

// ---------------------------------------------------------------------------
// fused gather (bf16 proj in) -> fp8 messages
// ---------------------------------------------------------------------------
__global__ void gather_msgs(const bf* __restrict__ proj_ip,
                            const bf* __restrict__ proj_pp,
                            const bf* __restrict__ proj_fl,
                            const int* __restrict__ rowptr,
                            const int* __restrict__ elist,
                            const float* __restrict__ b_ip,
                            const float* __restrict__ b_fl,
                            uint8_t* __restrict__ mq)
{
    int w = (blockIdx.x * blockDim.x + threadIdx.x) >> 5;
    int lane = threadIdx.x & 31;
    if (w >= N_NODES) return;
    int rp = rowptr[w], re = rowptr[w + 1];
    int deg = re - rp;
    int j = lane * 4;
    float v0 = 0.f, v1 = 0.f, v2 = 0.f, v3 = 0.f;

    if (deg > 0) {
        const bf* P; int ld, po;
        const bf* pd; int pld, ppo, local;
        const float* bs;
        if (w < G_PPFL)      { local = w;           P = proj_pp; ld = 512; po = 0;   pd = proj_ip; pld = 256; ppo = 128; bs = b_ip; }
        else if (w < G_FL)   { local = w - G_PPFL;  P = proj_fl; ld = 256; po = 0;   pd = proj_pp; pld = 512; ppo = 384; bs = b_fl; }
        else if (w < G_PPIP) { local = w - G_FL;    P = proj_pp; ld = 512; po = 256; pd = proj_fl; pld = 256; ppo = 128; bs = b_fl; }
        else                 { local = w - G_PPIP;  P = proj_ip; ld = 256; po = 0;   pd = proj_pp; pld = 512; ppo = 128; bs = b_ip; }

        for (int base = 0; base < deg; base += 32) {
            int eid = (rp + base + lane < re) ? elist[rp + base + lane] : 0;
            int lim = deg - base; if (lim > 32) lim = 32;
            for (int k = 0; k < lim; ++k) {
                int src = __shfl_sync(0xffffffff, eid, k);
                const __nv_bfloat162* pr = (const __nv_bfloat162*)(P + (size_t)src * ld + po + j);
                float2 a = __bfloat1622float2(pr[0]);
                float2 b = __bfloat1622float2(pr[1]);
                v0 += a.x; v1 += a.y; v2 += b.x; v3 += b.y;
            }
        }
        float rc = 1.f / (float)deg;
        const __nv_bfloat162* pp2 = (const __nv_bfloat162*)(pd + (size_t)local * pld + ppo + j);
        float2 pa = __bfloat1622float2(pp2[0]);
        float2 pb = __bfloat1622float2(pp2[1]);
        v0 = v0 * rc + pa.x + bs[j];
        v1 = v1 * rc + pa.y + bs[j + 1];
        v2 = v2 * rc + pb.x + bs[j + 2];
        v3 = v3 * rc + pb.y + bs[j + 3];
    }
    uint32_t pk = (uint32_t)pk2(v0, v1) | ((uint32_t)pk2(v2, v3) << 16);
    *(uint32_t*)(mq + (size_t)w * H + j) = pk;
}

// ---------------------------------------------------------------------------
// GRU elementwise: gates layout [rz(256) | gin(128) | ghn(128)] per row
// ---------------------------------------------------------------------------
__global__ void gru_elem(const bf* __restrict__ gmat,
                         bf* __restrict__ hb, uint8_t* __restrict__ hq, int Nn)
{
    int i = blockIdx.x * blockDim.x + threadIdx.x;
    if (i >= Nn * 64) return;
    int n = i >> 6, j = (i & 63) * 2;
    const bf* gr = gmat + (size_t)n * 512;
    float2 rr = __bfloat1622float2(*(const __nv_bfloat162*)(gr + j));
    float2 zz = __bfloat1622float2(*(const __nv_bfloat162*)(gr + 128 + j));
    float2 gi = __bfloat1622float2(*(const __nv_bfloat162*)(gr + 256 + j));
    float2 gh = __bfloat1622float2(*(const __nv_bfloat162*)(gr + 384 + j));
    float2 hv = __bfloat1622float2(*(const __nv_bfloat162*)(hb + (size_t)n * H + j));

    float r0 = 1.f / (1.f + expf(-rr.x));
    float r1 = 1.f / (1.f + expf(-rr.y));
    float z0 = 1.f / (1.f + expf(-zz.x));
    float z1 = 1.f / (1.f + expf(-zz.y));
    float n0 = tanhf(gi.x + r0 * gh.x);
    float n1 = tanhf(gi.y + r1 * gh.y);
    float o0 = (1.f - z0) * n0 + z0 * hv.x;
    float o1 = (1.f - z1) * n1 + z1 * hv.y;

    *(__nv_bfloat162*)(hb + (size_t)n * H + j) = __floats2bfloat162_rn(o0, o1);
    *(uint16_t*)(hq + (size_t)n * H + j) = pk2(o0, o1);
}

// ---------------------------------------------------------------------------
// init
// ---------------------------------------------------------------------------
__global__ void prep_weights(const float* __restrict__ wmi, const float* __restrict__ wmf,
                             const float* __restrict__ wii, const float* __restrict__ whi,
                             const float* __restrict__ wif, const float* __restrict__ whf,
                             const float* __restrict__ w1,  const float* __restrict__ w2,
                             const float* __restrict__ bii, const float* __restrict__ bhi,
                             const float* __restrict__ bif, const float* __restrict__ bhf,
                             bf* __restrict__ wb, uint8_t* __restrict__ wq,
                             float* __restrict__ bias,
                             int* __restrict__ cnt, int* __restrict__ cursor)
{
    int t = blockIdx.x * blockDim.x + threadIdx.x;
    if (t < N_NODES) { cnt[t] = 0; cursor[t] = 0; }
    if (t < 256) bias[t] = bii[t] + bhi[t];
    else if (t < 512) bias[t] = bif[t - 256] + bhf[t - 256];
    if (t >= (int)(WB_TOTAL / 2)) return;
    float v[2];
#pragma unroll
    for (int q = 0; q < 2; ++q) {
        int i = 2 * t + q;
        if (i < 65536) {
            const float* s = (i < 32768) ? wmi : wmf;
            int o = i & 32767;
            int n = o >> 7, k = o & 127;
            v[q] = (n < 128) ? s[n * 256 + k] : s[(n - 128) * 256 + 128 + k];
        } else if (i < 114688) v[q] = wii[i - 65536];
        else if (i < 163840)   v[q] = whi[i - 114688];
        else if (i < 212992)   v[q] = wif[i - 163840];
        else if (i < 262144)   v[q] = whf[i - 212992];
        else if (i < 278528)   v[q] = w1[i - 262144];
        else                   v[q] = w2[i - 278528];
    }
    *(__nv_bfloat162*)(wb + 2 * t) = __floats2bfloat162_rn(v[0], v[1]);
    *(uint16_t*)(wq + 2 * t) = pk2(v[0], v[1]);
}

__global__ void init_states(const float* __restrict__ x_ip,
                            const float* __restrict__ x_pp,
                            const float* __restrict__ x_fl,
                            bf* __restrict__ hb, uint8_t* __restrict__ hq)
{
    int t = blockIdx.x * blockDim.x + threadIdx.x;
    if (t >= HB_ROWS * 64) return;
    int n = t >> 6, j = (t & 63) * 2;
    float v0, v1;
    if (n < HB_PP) {
        v0 = x_ip[(size_t)n * H + j]; v1 = x_ip[(size_t)n * H + j + 1];
    } else if (n < HB_FL) {
        const float* r = x_pp + (size_t)(n - HB_PP) * H;
        v0 = r[j]; v1 = r[j + 1];
    } else {
        const float* r = x_fl + (size_t)(n - HB_FL) * IN_C;
        v0 = (j < IN_C) ? r[j] : 0.f;
        v1 = (j + 1 < IN_C) ? r[j + 1] : 0.f;
    }
    *(__nv_bfloat162*)(hb + (size_t)n * H + j) = __floats2bfloat162_rn(v0, v1);
    *(uint16_t*)(hq + (size_t)n * H + j) = pk2(v0, v1);
}

__global__ void readout_final(const bf* __restrict__ r2,
                              const float* __restrict__ W3,
                              const float* __restrict__ b3,
                              float* __restrict__ out)
{
    int n = blockIdx.x * blockDim.x + threadIdx.x;
    if (n >= N_FL) return;
    float l0 = b3[0], l1 = b3[1];
    const bf* r = r2 + (size_t)n * 64;
#pragma unroll
    for (int k = 0; k < 64; ++k) {
        float rv = __bfloat162float(r[k]);
        l0 = fmaf(rv, W3[k], l0);
        l1 = fmaf(rv, W3[64 + k], l1);
    }
    out[2 * n + 0] = 1.f / (1.f + expf(l1 - l0));
    out[2 * n + 1] = 1.f / (1.f + expf(l0 - l1));
}

// ---------------------------------------------------------------------------
// Host orchestration
// ---------------------------------------------------------------------------
static constexpr int GSMEM = 4 * 5120 * 2 * 2;  // 81920 B (bf16 kernel)

struct JobSpec {
    const void* A; const void* W; const void* A2; const void* W2;
    const float* bias; bf* C;
    int M, N, ldc, cofs, relu;
};

static void fill_jobs(Jobs& js, const JobSpec* sp, int nj, int bnw, int& tiles)
{
    js.njobs = nj;
    tiles = 0;
    for (int k = 0; k < nj; ++k) {
        Job& J = js.j[k];
        J.A = sp[k].A; J.W = sp[k].W; J.A2 = sp[k].A2; J.W2 = sp[k].W2;
        J.bias = sp[k].bias; J.C = sp[k].C;
        J.M = sp[k].M; J.N = sp[k].N; J.ldc = sp[k].ldc; J.cofs = sp[k].cofs;
        J.relu = sp[k].relu;
        J.nx = (sp[k].N + bnw - 1) / bnw;
        J.tile_start = tiles;
        tiles += J.nx * ((sp[k].M + 127) / 128);
    }
    for (int k = nj; k < 6; ++k) js.j[k] = js.j[nj - 1];
}

static inline void launch_jobs8(const JobSpec* sp, int nj)
{
    Jobs js; int tiles;
    fill_jobs(js, sp, nj, 64, tiles);
    bgemm8<<<tiles, 256>>>(js);
}

static inline void launch_jobs16(const JobSpec* sp, int nj)
{
    static int attr_set = 0;
    if (!attr_set) {
        cudaFuncSetAttribute(bgemm, cudaFuncAttributeMaxDynamicSharedMemorySize, GSMEM);
        attr_set = 1;
    }
    Jobs js; int tiles;
    fill_jobs(js, sp, nj, 128, tiles);
    bgemm<<<tiles, 256, GSMEM>>>(js);
}

extern "C" void kernel_launch(void* const* d_in, const int* in_sizes, int n_in,
                              void* d_out, int out_size)
{
    (void)in_sizes; (void)n_in; (void)out_size;

    const float* x_ip     = (const float*)d_in[0];
    const float* x_pp     = (const float*)d_in[1];
    const float* x_fl     = (const float*)d_in[2];
    const float* W_msg_ip = (const float*)d_in[3];
    const float* b_msg_ip = (const float*)d_in[4];
    const float* W_msg_fl = (const float*)d_in[5];
    const float* b_msg_fl = (const float*)d_in[6];
    const float* w_ih_ip  = (const float*)d_in[7];
    const float* w_hh_ip  = (const float*)d_in[8];
    const float* b_ih_ip  = (const float*)d_in[9];
    const float* b_hh_ip  = (const float*)d_in[10];
    const float* w_ih_fl  = (const float*)d_in[11];
    const float* w_hh_fl  = (const float*)d_in[12];
    const float* b_ih_fl  = (const float*)d_in[13];
    const float* b_hh_fl  = (const float*)d_in[14];
    const float* W1       = (const float*)d_in[15];
    const float* b1       = (const float*)d_in[16];
    const float* W2       = (const float*)d_in[17];
    const float* b2       = (const float*)d_in[18];
    const float* W3       = (const float*)d_in[19];
    const float* b3       = (const float*)d_in[20];
    const int* src_ip2pp  = (const int*)d_in[21];
    const int* dst_ip2pp  = (const int*)d_in[22];
    const int* src_pp2ip  = (const int*)d_in[23];
    const int* dst_pp2ip  = (const int*)d_in[24];
    const int* src_pp2fl  = (const int*)d_in[25];
    const int* dst_pp2fl  = (const int*)d_in[26];
    const int* src_fl2pp  = (const int*)d_in[27];
    const int* dst_fl2pp  = (const int*)d_in[28];
    float* out = (float*)d_out;

    bf* bb;       cudaGetSymbolAddress((void**)&bb, d_b16);
    uint8_t* qb;  cudaGetSymbolAddress((void**)&qb, d_fp8);
    float* biasb; cudaGetSymbolAddress((void**)&biasb, d_bias);
    int* cnt;     cudaGetSymbolAddress((void**)&cnt, d_cnt);
    int* cursor;  cudaGetSymbolAddress((void**)&cursor, d_cursor);
    int* rowptr;  cudaGetSymbolAddress((void**)&rowptr, d_rowptr);
    int* elist;   cudaGetSymbolAddress((void**)&elist, d_elist);
    int* bsum;    cudaGetSymbolAddress((void**)&bsum, d_bsum);
    int* boff;    cudaGetSymbolAddress((void**)&boff, d_boff);

    bf* hb      = bb + B_HB;
    bf* hb_pp   = hb + (size_t)HB_PP * H;
    bf* hb_fl   = hb + (size_t)HB_FL * H;
    bf* proj_ip = bb + B_PROJ_IP;
    bf* proj_pp = bb + B_PROJ_PP;
    bf* proj_fl = bb + B_PROJ_FL;
    bf* gmat    = bb + B_G;
    bf* gmat2   = bb + B_G2;
    bf* r1      = bb + B_R1;
    bf* r2      = bb + B_R2;
    bf* wb      = bb + B_WB;

    uint8_t* hq    = qb + Q_HQ;
    uint8_t* hq_pp = hq + (size_t)HB_PP * H;
    uint8_t* hq_fl = hq + (size_t)HB_FL * H;
    uint8_t* mq    = qb + Q_MQ;
    uint8_t* wq    = qb + Q_WQ;

    bf* wb_w1 = wb + WB_W1;
    bf* wb_w2 = wb + WB_W2;
    uint8_t* wq_msg   = wq + WB_MSG;
    uint8_t* wq_ih_ip = wq + WB_IH_IP;
    uint8_t* wq_hh_ip = wq + WB_HH_IP;
    uint8_t* wq_ih_fl = wq + WB_IH_FL;
    uint8_t* wq_hh_fl = wq + WB_HH_FL;

    // --- init; launch #4 = first fp8 bgemm (profiled by ncu) ---
    {
        int g = (N_NODES > (int)(WB_TOTAL / 2)) ? N_NODES : (int)(WB_TOTAL / 2);
        prep_weights<<<(g + 255) / 256, 256>>>(
            W_msg_ip, W_msg_fl, w_ih_ip, w_hh_ip, w_ih_fl, w_hh_fl, W1, W2,
            b_ih_ip, b_hh_ip, b_ih_fl, b_hh_fl,
            wb, wq, biasb, cnt, cursor);
    }
    init_states<<<(HB_ROWS * 64 + 255) / 256, 256>>>(x_ip, x_pp, x_fl, hb, hq);
    edge_hist<<<(4 * E_CNT + 255) / 256, 256>>>(dst_ip2pp, dst_pp2ip, dst_pp2fl, dst_fl2pp, cnt);

    // projections for iter 0 (bf16 out)
    {
        JobSpec sp[3] = {
            { hq,    wq_msg,             nullptr, nullptr, nullptr, proj_ip, N_IP, 256, 256, 0, 0 },
            { hq_fl, wq_msg + 256 * 128, nullptr, nullptr, nullptr, proj_fl, N_FL, 256, 256, 0, 0 },
            { hq_pp, wq_msg,             nullptr, nullptr, nullptr, proj_pp, N_PP, 512, 512, 0, 0 },
        };
        launch_jobs8(sp, 3);
    }

    scan_part<<<SC_NB, SC_T>>>(cnt, bsum);
    scan_top<<<1, 128>>>(bsum, boff);
    scan_final<<<SC_NB, SC_T>>>(cnt, boff, rowptr);
    edge_fill<<<(4 * E_CNT + 255) / 256, 256>>>(src_ip2pp, dst_ip2pp, src_pp2ip, dst_pp2ip,
                                                src_pp2fl, dst_pp2fl, src_fl2pp, dst_fl2pp,
                                                rowptr, cursor, elist);

    for (int it = 0; it < N_ITER; ++it) {
        // 1. gather -> fp8 messages
        gather_msgs<<<(N_NODES * 32 + 255) / 256, 256>>>(proj_ip, proj_pp, proj_fl,
                                                         rowptr, elist, b_msg_ip, b_msg_fl, mq);

        // 2. GRU phase A: fused rz (K=256 split) + separate n-gate halves; 6 jobs
        {
            JobSpec sp[6] = {
                { mq,                    wq_ih_ip,             hq,    wq_hh_ip,             biasb,          gmat,                      70000, 256, 512, 0,   0 },
                { mq,                    wq_ih_ip + 256 * 128, nullptr, nullptr,            b_ih_ip + 256,  gmat,                      70000, 128, 512, 256, 0 },
                { hq,                    wq_hh_ip + 256 * 128, nullptr, nullptr,            b_hh_ip + 256,  gmat,                      70000, 128, 512, 384, 0 },
                { mq + (size_t)G_FL * H, wq_ih_fl,             hq_fl, wq_hh_fl,             biasb + 256,    gmat + (size_t)70000*512,  N_FL,  256, 512, 0,   0 },
                { mq + (size_t)G_FL * H, wq_ih_fl + 256 * 128, nullptr, nullptr,            b_ih_fl + 256,  gmat + (size_t)70000*512,  N_FL,  128, 512, 256, 0 },
                { hq_fl,                 wq_hh_fl + 256 * 128, nullptr, nullptr,            b_hh_fl + 256,  gmat + (size_t)70000*512,  N_FL,  128, 512, 384, 0 },
            };
            launch_jobs8(sp, 6);
        }
        gru_elem<<<(HB_ROWS * 64 + 255) / 256, 256>>>(gmat, hb, hq, HB_ROWS);

        // 3. GRU phase B: pp(ip2pp) gates (needs updated h_pp) + next-iter ip/fl projections
        {
            JobSpec sp[5] = {
                { mq + (size_t)G_PPIP * H, wq_ih_ip,             hq_pp, wq_hh_ip,  biasb,         gmat2,   N_PP, 256, 512, 0,   0 },
                { mq + (size_t)G_PPIP * H, wq_ih_ip + 256 * 128, nullptr, nullptr, b_ih_ip + 256, gmat2,   N_PP, 128, 512, 256, 0 },
                { hq_pp,                   wq_hh_ip + 256 * 128, nullptr, nullptr, b_hh_ip + 256, gmat2,   N_PP, 128, 512, 384, 0 },
                { hq,                      wq_msg,               nullptr, nullptr, nullptr,       proj_ip, N_IP, 256, 256, 0,   0 },
                { hq_fl,                   wq_msg + 256 * 128,   nullptr, nullptr, nullptr,       proj_fl, N_FL, 256, 256, 0,   0 },
            };
            launch_jobs8(sp, (it < N_ITER - 1) ? 5 : 3);
        }
        gru_elem<<<(N_PP * 64 + 255) / 256, 256>>>(gmat2, hb_pp, hq_pp, N_PP);

        // 4. proj_pp for next iter (needs updated h_pp)
        if (it < N_ITER - 1) {
            JobSpec sp[1] = {
                { hq_pp, wq_msg, nullptr, nullptr, nullptr, proj_pp, N_PP, 512, 512, 0, 0 },
            };
            launch_jobs8(sp, 1);
        }
    }

    // readout (bf16)
    {
        JobSpec sp1[1] = { { hb_fl, wb_w1, nullptr, nullptr, b1, r1, N_FL, 128, 128, 0, 1 } };
        launch_jobs16(sp1, 1);
        JobSpec sp2[1] = { { r1, wb_w2, nullptr, nullptr, b2, r2, N_FL, 64, 64, 0, 1 } };
        launch_jobs16(sp2, 1);
    }
    readout_final<<<(N_FL + 127) / 128, 128>>>(r2, W3, b3, out);
}

// round 17
// speedup vs baseline: 1.1144x; 1.1144x over previous
#include <cuda_runtime.h>
#include <cuda_bf16.h>
#include <math.h>
#include <stdint.h>

#define H 128
#define IN_C 32
#define N_IP 20000
#define N_PP 50000
#define N_FL 100000
#define E_CNT 200000
#define N_ITER 4
#define N_NODES 220000

// message/node-space ordering: [ip | pp_fl | fl | pp_ip]
#define G_IP    0
#define G_PPFL  20000
#define G_FL    70000
#define G_PPIP  170000
// h ordering: [ip | pp | fl]
#define HB_IP   0
#define HB_PP   20000
#define HB_FL   70000
#define HB_ROWS 170000

typedef __nv_bfloat16 bf;

// ---------------------------------------------------------------------------
// Scratch
// ---------------------------------------------------------------------------
static constexpr size_t B_HB      = 0;                                  // bf16 h, 170000 x 128
static constexpr size_t B_PROJ_IP = B_HB      + (size_t)HB_ROWS * H;    // [Ws_ip|Wd_ip] ld 256
static constexpr size_t B_PROJ_PP = B_PROJ_IP + (size_t)N_IP * 2 * H;   // ld 512
static constexpr size_t B_PROJ_FL = B_PROJ_PP + (size_t)N_PP * 4 * H;   // ld 256
static constexpr size_t B_G       = B_PROJ_FL + (size_t)N_FL * 2 * H;   // gates [rz|gin|ghn] 170000 x 512
static constexpr size_t B_G2      = B_G       + (size_t)HB_ROWS * 512;  // 50000 x 512
static constexpr size_t B_R1      = B_G2      + (size_t)N_PP * 512;
static constexpr size_t B_R2      = B_R1      + (size_t)N_FL * H;
static constexpr size_t B_WB      = B_R2      + (size_t)N_FL * 64;
static constexpr size_t WB_MSG    = 0;                                  // [512][128]
static constexpr size_t WB_IH_IP  = WB_MSG    + 65536;
static constexpr size_t WB_HH_IP  = WB_IH_IP  + 49152;
static constexpr size_t WB_IH_FL  = WB_HH_IP  + 49152;
static constexpr size_t WB_HH_FL  = WB_IH_FL  + 49152;
static constexpr size_t WB_W1     = WB_HH_FL  + 49152;
static constexpr size_t WB_W2     = WB_W1     + 16384;
static constexpr size_t WB_TOTAL  = WB_W2     + 8192;                   // 295936 (even)
static constexpr size_t B_TOTAL   = B_WB + WB_TOTAL;
__device__ bf d_b16[B_TOTAL];

// fp8 regions (bytes)
static constexpr size_t Q_HQ    = 0;                                    // 170000 x 128
static constexpr size_t Q_MQ    = Q_HQ + (size_t)HB_ROWS * H;           // 220000 x 128
static constexpr size_t Q_WQ    = Q_MQ + (size_t)N_NODES * H;
static constexpr size_t Q_TOTAL = Q_WQ + WB_TOTAL;
__device__ uint8_t d_fp8[Q_TOTAL];

__device__ float d_bias[512];   // [0:256) = b_ih_ip+b_hh_ip, [256:512) = b_ih_fl+b_hh_fl

__device__ int d_cnt[N_NODES];
__device__ int d_cursor[N_NODES];
__device__ int d_rowptr[N_NODES + 1];
__device__ int d_elist[4 * E_CNT];

#define SC_T 512
#define SC_I 4
#define SC_C (SC_T * SC_I)
#define SC_NB ((N_NODES + SC_C - 1) / SC_C)
__device__ int d_bsum[128];
__device__ int d_boff[128];

// ---------------------------------------------------------------------------
// asm helpers
// ---------------------------------------------------------------------------
#define CPA16(dst, src, sz) \
    asm volatile("cp.async.cg.shared.global [%0], [%1], 16, %2;" \
                 :: "r"(dst), "l"(src), "r"(sz))

#define LDSM4(r0, r1, r2, r3, addr) \
    asm volatile("ldmatrix.sync.aligned.m8n8.x4.shared.b16 {%0,%1,%2,%3}, [%4];" \
                 : "=r"(r0), "=r"(r1), "=r"(r2), "=r"(r3) : "r"(addr))

#define MMA_BF16(d, a, b) \
    asm volatile("mma.sync.aligned.m16n8k16.row.col.f32.bf16.bf16.f32 " \
        "{%0,%1,%2,%3}, {%4,%5,%6,%7}, {%8,%9}, {%0,%1,%2,%3};" \
        : "+f"((d)[0]), "+f"((d)[1]), "+f"((d)[2]), "+f"((d)[3]) \
        : "r"((a)[0]), "r"((a)[1]), "r"((a)[2]), "r"((a)[3]), \
          "r"((b)[0]), "r"((b)[1]))

#define MMA_FP8(d, a, b) \
    asm volatile("mma.sync.aligned.m16n8k32.row.col.f32.e4m3.e4m3.f32 " \
        "{%0,%1,%2,%3}, {%4,%5,%6,%7}, {%8,%9}, {%0,%1,%2,%3};" \
        : "+f"((d)[0]), "+f"((d)[1]), "+f"((d)[2]), "+f"((d)[3]) \
        : "r"((a)[0]), "r"((a)[1]), "r"((a)[2]), "r"((a)[3]), \
          "r"((b)[0]), "r"((b)[1]))

__device__ __forceinline__ uint32_t scvta(const void* p) {
    return (uint32_t)__cvta_generic_to_shared(p);
}
__device__ __forceinline__ uint16_t pk2(float lo, float hi) {
    uint16_t r;
    asm("cvt.rn.satfinite.e4m3x2.f32 %0, %1, %2;" : "=h"(r) : "f"(hi), "f"(lo));
    return r;
}
// fast sigmoid / tanh (MUFU); error << bf16 storage quantization
__device__ __forceinline__ float fsig(float x) {
    float e;
    asm("ex2.approx.f32 %0, %1;" : "=f"(e) : "f"(-x * 1.4426950408889634f));
    float r;
    asm("rcp.approx.f32 %0, %1;" : "=f"(r) : "f"(1.f + e));
    return r;
}
__device__ __forceinline__ float ftanh(float x) {
    float y;
    asm("tanh.approx.f32 %0, %1;" : "=f"(y) : "f"(x));
    return y;
}

// ---------------------------------------------------------------------------
// Job table (up to 6 jobs, 1-D grid over tiles).
// A2/W2 non-null => K=256 split mode: k[0:128) from A/W, k[128:256) from A2/W2.
// ---------------------------------------------------------------------------
struct Job {
    const void* A; const void* W; const void* A2; const void* W2;
    const float* bias; bf* C;
    int M, N, ldc, cofs, relu, tile_start, nx, pad;
};
struct Jobs { Job j[6]; int njobs; };

__device__ __forceinline__ int job_select(const Jobs& js, int t) {
    int ji = 0;
#pragma unroll
    for (int k = 1; k < 6; ++k)
        if (js.njobs > k && t >= js.j[k].tile_start) ji = k;
    return ji;
}

// ---------------------------------------------------------------------------
// FP8 mma GEMM: C[m, cofs+n] = sum_k A[m,k]*W[n*128+k] (+bias)(+relu), bf16 out
// Tile 128m x 64n, 8 warps (4m x 2n), acc 32 regs/thread -> 3 CTAs/SM.
// K=128 in 2 stages (K64 each); K=256 via A2/W2 ping-pong.
// ---------------------------------------------------------------------------
__global__ void __launch_bounds__(256, 3)
bgemm8(Jobs js)
{
    const int t = blockIdx.x;
    const Job J = js.j[job_select(js, t)];
    const int lt = t - J.tile_start;
    const int bn = (lt % J.nx) * 64;
    const int bm = (lt / J.nx) * 128;

    __shared__ __align__(16) uint16_t As[2][128][40];
    __shared__ __align__(16) uint16_t Bs[2][64][40];

    const int tid  = threadIdx.x;
    const int wid  = tid >> 5;
    const int lane = tid & 31;
    const int g    = lane >> 2;
    const int t4   = lane & 3;
    const int wm   = (wid >> 1) * 32;    // 4 m-groups of 32 rows
    const int wn   = (wid & 1) * 32;     // 2 n-groups of 32 cols

    const int lr  = tid >> 1;            // A row 0..127
    const int ha  = tid & 1;             // 32B half of A's 64B stage chunk
    const int rb  = tid >> 2;            // B row 0..63
    const int hb4 = tid & 3;             // 16B quarter of B's 64B stage chunk

    int arow = bm + lr;
    const uint32_t asz = (arow < J.M) ? 16u : 0u;
    if (arow >= J.M) arow = J.M - 1;
    const uint8_t* ap = (const uint8_t*)J.A + (size_t)arow * 128 + ha * 32;

    int brow = bn + rb;
    const uint32_t bsz = (brow < J.N) ? 16u : 0u;
    if (brow >= J.N) brow = J.N - 1;
    const uint8_t* bp = (const uint8_t*)J.W + (size_t)brow * 128 + hb4 * 16;

#define ISSUE8(buf, aptr, bptr)                                        \
    { uint32_t da = scvta(&As[buf][lr][ha * 16]);                      \
      uint32_t db = scvta(&Bs[buf][rb][hb4 * 8]);                      \
      CPA16(da, (aptr), asz); CPA16(da + 16, (aptr) + 16, asz);        \
      CPA16(db, (bptr), bsz);                                          \
      asm volatile("cp.async.commit_group;" ::: "memory"); }

    ISSUE8(0, ap, bp)
    ISSUE8(1, ap + 64, bp + 64)

    float acc[2][4][4];
#pragma unroll
    for (int i = 0; i < 2; ++i)
#pragma unroll
        for (int j = 0; j < 4; ++j)
#pragma unroll
            for (int k = 0; k < 4; ++k) acc[i][j][k] = 0.f;

#define COMPUTE8(s)                                                            \
    {                                                                          \
        _Pragma("unroll")                                                      \
        for (int kk = 0; kk < 2; ++kk) {                                       \
            uint32_t a[2][4];                                                  \
            _Pragma("unroll")                                                  \
            for (int mt = 0; mt < 2; ++mt) {                                   \
                uint32_t ad = scvta(&As[s][wm + mt * 16 + (lane & 15)]         \
                                        [kk * 16 + ((lane >> 4) << 3)]);       \
                LDSM4(a[mt][0], a[mt][1], a[mt][2], a[mt][3], ad);             \
            }                                                                  \
            uint32_t b[4][2];                                                  \
            _Pragma("unroll")                                                  \
            for (int p = 0; p < 2; ++p) {                                      \
                uint32_t ad = scvta(&Bs[s][wn + p * 16 + ((lane >> 4) & 1) * 8 \
                                           + (lane & 7)]                       \
                                        [kk * 16 + ((lane >> 3) & 1) * 8]);    \
                uint32_t r0, r1, r2, r3;                                       \
                LDSM4(r0, r1, r2, r3, ad);                                     \
                b[2 * p][0] = r0; b[2 * p][1] = r1;                            \
                b[2 * p + 1][0] = r2; b[2 * p + 1][1] = r3;                    \
            }                                                                  \
            _Pragma("unroll")                                                  \
            for (int mt = 0; mt < 2; ++mt)                                     \
                _Pragma("unroll")                                              \
                for (int nt = 0; nt < 4; ++nt)                                 \
                    MMA_FP8(acc[mt][nt], a[mt], b[nt]);                        \
        }                                                                      \
    }

#define WAITG(n) asm volatile("cp.async.wait_group " #n ";" ::: "memory")

    if (J.A2 == nullptr) {
        WAITG(1); __syncthreads(); COMPUTE8(0);
        WAITG(0); __syncthreads(); COMPUTE8(1);
    } else {
        const uint8_t* ap2 = (const uint8_t*)J.A2 + (size_t)arow * 128 + ha * 32;
        const uint8_t* bp2 = (const uint8_t*)J.W2 + (size_t)brow * 128 + hb4 * 16;
        WAITG(1); __syncthreads(); COMPUTE8(0); __syncthreads();
        ISSUE8(0, ap2, bp2)
        WAITG(1); __syncthreads(); COMPUTE8(1); __syncthreads();
        ISSUE8(1, ap2 + 64, bp2 + 64)
        WAITG(1); __syncthreads(); COMPUTE8(0);
        WAITG(0); __syncthreads(); COMPUTE8(1);
    }
#undef WAITG
#undef COMPUTE8
#undef ISSUE8

#pragma unroll
    for (int mt = 0; mt < 2; ++mt) {
#pragma unroll
        for (int hf = 0; hf < 2; ++hf) {
            int row = bm + wm + mt * 16 + g + hf * 8;
            if (row >= J.M) continue;
#pragma unroll
            for (int nt = 0; nt < 4; ++nt) {
                int col = bn + wn + nt * 8 + 2 * t4;
                if (col >= J.N) continue;
                float v0 = acc[mt][nt][hf * 2 + 0];
                float v1 = acc[mt][nt][hf * 2 + 1];
                if (J.bias) { v0 += J.bias[col]; v1 += J.bias[col + 1]; }
                if (J.relu) { v0 = fmaxf(v0, 0.f); v1 = fmaxf(v1, 0.f); }
                *(__nv_bfloat162*)(J.C + (size_t)row * J.ldc + J.cofs + col) =
                    __floats2bfloat162_rn(v0, v1);
            }
        }
    }
}

// ---------------------------------------------------------------------------
// bf16 mma GEMM (readout only; 128-wide tiles)
// ---------------------------------------------------------------------------
__global__ void __launch_bounds__(256, 2)
bgemm(Jobs js)
{
    const int t = blockIdx.x;
    const Job J = js.j[job_select(js, t)];
    const int lt = t - J.tile_start;
    const int bn = (lt % J.nx) * 128;
    const int bm = (lt / J.nx) * 128;

    extern __shared__ __align__(16) char dsm[];
    bf* As = (bf*)dsm;
    bf* Bs = (bf*)dsm + 4 * 5120;

    const int tid  = threadIdx.x;
    const int wid  = tid >> 5;
    const int lane = tid & 31;
    const int g    = lane >> 2;
    const int t4   = lane & 3;
    const int wm   = (wid & 1) * 64;
    const int wn   = (wid >> 1) * 32;

    const int lr = tid >> 1;
    const int kc = (tid & 1) * 16;

    int arow = bm + lr;
    const uint32_t asz = (arow < J.M) ? 16u : 0u;
    if (arow >= J.M) arow = J.M - 1;
    const bf* ap = (const bf*)J.A + (size_t)arow * 128 + kc;

    int brow = bn + lr;
    const uint32_t bsz = (brow < J.N) ? 16u : 0u;
    if (brow >= J.N) brow = J.N - 1;
    const bf* bp = (const bf*)J.W + (size_t)brow * 128 + kc;

#pragma unroll
    for (int st = 0; st < 4; ++st) {
        uint32_t da = scvta(As + st * 5120 + lr * 40 + kc);
        uint32_t db = scvta(Bs + st * 5120 + lr * 40 + kc);
        CPA16(da, ap + st * 32, asz); CPA16(da + 16, ap + st * 32 + 8, asz);
        CPA16(db, bp + st * 32, bsz); CPA16(db + 16, bp + st * 32 + 8, bsz);
        asm volatile("cp.async.commit_group;" ::: "memory");
    }

    float acc[4][4][4];
#pragma unroll
    for (int i = 0; i < 4; ++i)
#pragma unroll
        for (int j = 0; j < 4; ++j)
#pragma unroll
            for (int k = 0; k < 4; ++k) acc[i][j][k] = 0.f;

#define STAGE(s, WG)                                                           \
    {                                                                          \
        asm volatile("cp.async.wait_group " #WG ";" ::: "memory");             \
        __syncthreads();                                                       \
        const bf* as = As + (s) * 5120;                                        \
        const bf* bs_ = Bs + (s) * 5120;                                       \
        _Pragma("unroll")                                                      \
        for (int kk = 0; kk < 32; kk += 16) {                                  \
            uint32_t a[4][4];                                                  \
            _Pragma("unroll")                                                  \
            for (int mt = 0; mt < 4; ++mt) {                                   \
                uint32_t ad = scvta(as + (wm + mt * 16 + (lane & 15)) * 40     \
                                        + kk + ((lane >> 4) << 3));            \
                LDSM4(a[mt][0], a[mt][1], a[mt][2], a[mt][3], ad);             \
            }                                                                  \
            uint32_t b[4][2];                                                  \
            _Pragma("unroll")                                                  \
            for (int p = 0; p < 2; ++p) {                                      \
                int br = wn + p * 16 + ((lane >> 4) & 1) * 8 + (lane & 7);     \
                int bc = kk + ((lane >> 3) & 1) * 8;                           \
                uint32_t r0, r1, r2, r3;                                       \
                LDSM4(r0, r1, r2, r3, scvta(bs_ + br * 40 + bc));              \
                b[2 * p][0] = r0; b[2 * p][1] = r1;                            \
                b[2 * p + 1][0] = r2; b[2 * p + 1][1] = r3;                    \
            }                                                                  \
            _Pragma("unroll")                                                  \
            for (int mt = 0; mt < 4; ++mt)                                     \
                _Pragma("unroll")                                              \
                for (int nt = 0; nt < 4; ++nt)                                 \
                    MMA_BF16(acc[mt][nt], a[mt], b[nt]);                       \
        }                                                                      \
    }

    STAGE(0, 3)
    STAGE(1, 2)
    STAGE(2, 1)
    STAGE(3, 0)
#undef STAGE

#pragma unroll
    for (int mt = 0; mt < 4; ++mt) {
#pragma unroll
        for (int hf = 0; hf < 2; ++hf) {
            int row = bm + wm + mt * 16 + g + hf * 8;
            if (row >= J.M) continue;
#pragma unroll
            for (int nt = 0; nt < 4; ++nt) {
                int col = bn + wn + nt * 8 + 2 * t4;
                if (col >= J.N) continue;
                float v0 = acc[mt][nt][hf * 2 + 0];
                float v1 = acc[mt][nt][hf * 2 + 1];
                if (J.bias) { v0 += J.bias[col]; v1 += J.bias[col + 1]; }
                if (J.relu) { v0 = fmaxf(v0, 0.f); v1 = fmaxf(v1, 0.f); }
                *(__nv_bfloat162*)(J.C + (size_t)row * J.ldc + J.cofs + col) =
                    __floats2bfloat162_rn(v0, v1);
            }
        }
    }
}

// ---------------------------------------------------------------------------
// CSR build
// ---------------------------------------------------------------------------
__device__ __forceinline__ int seg_base(int set) {
    return (set == 0) ? G_PPIP : (set == 1) ? G_IP : (set == 2) ? G_FL : G_PPFL;
}

__global__ void edge_hist(const int* __restrict__ d0, const int* __restrict__ d1,
                          const int* __restrict__ d2, const int* __restrict__ d3,
                          int* __restrict__ cnt)
{
    int i = blockIdx.x * blockDim.x + threadIdx.x;
    if (i >= 4 * E_CNT) return;
    int set = i / E_CNT, e = i - set * E_CNT;
    const int* d = (set == 0) ? d0 : (set == 1) ? d1 : (set == 2) ? d2 : d3;
    atomicAdd(cnt + seg_base(set) + d[e], 1);
}

__global__ void scan_part(const int* __restrict__ cnt, int* __restrict__ bsum)
{
    __shared__ int sh[SC_T];
    int b = blockIdx.x, t = threadIdx.x;
    int base = b * SC_C + t * SC_I;
    int s = 0;
#pragma unroll
    for (int k = 0; k < SC_I; ++k) {
        int idx = base + k;
        if (idx < N_NODES) s += cnt[idx];
    }
    sh[t] = s;
    __syncthreads();
    for (int off = SC_T / 2; off > 0; off >>= 1) {
        if (t < off) sh[t] += sh[t + off];
        __syncthreads();
    }
    if (t == 0) bsum[b] = sh[0];
}

__global__ void scan_top(const int* __restrict__ bsum, int* __restrict__ boff)
{
    __shared__ int sh[128];
    int t = threadIdx.x;
    int v = (t < SC_NB) ? bsum[t] : 0;
    sh[t] = v;
    __syncthreads();
    for (int off = 1; off < 128; off <<= 1) {
        int u = (t >= off) ? sh[t - off] : 0;
        __syncthreads();
        sh[t] += u;
        __syncthreads();
    }
    if (t < SC_NB) boff[t] = sh[t] - v;
}

__global__ void scan_final(const int* __restrict__ cnt, const int* __restrict__ boff,
                           int* __restrict__ rowptr)
{
    __shared__ int sh[SC_T];
    int b = blockIdx.x, t = threadIdx.x;
    int base = b * SC_C + t * SC_I;
    int loc[SC_I];
    int s = 0;
#pragma unroll
    for (int k = 0; k < SC_I; ++k) {
        int idx = base + k;
        loc[k] = (idx < N_NODES) ? cnt[idx] : 0;
        s += loc[k];
    }
    sh[t] = s;
    __syncthreads();
    for (int off = 1; off < SC_T; off <<= 1) {
        int u = (t >= off) ? sh[t - off] : 0;
        __syncthreads();
        sh[t] += u;
        __syncthreads();
    }
    int run = boff[b] + sh[t] - s;
#pragma unroll
    for (int k = 0; k < SC_I; ++k) {
        int idx = base + k;
        if (idx < N_NODES) { rowptr[idx] = run; run += loc[k]; }
    }
    if (b == 0 && t == 0) rowptr[N_NODES] = 4 * E_CNT;
}

__global__ void edge_fill(const int* __restrict__ s0, const int* __restrict__ d0,
                          const int* __restrict__ s1, const int* __restrict__ d1,
                          const int* __restrict__ s2, const int* __restrict__ d2,
                          const int* __restrict__ s3, const int* __restrict__ d3,
                          const int* __restrict__ rowptr, int* __restrict__ cursor,
                          int* __restrict__ elist)
{
    int i = blockIdx.x * blockDim.x + threadIdx.x;
    if (i >= 4 * E_CNT) return;
    int set = i / E_CNT, e = i - set * E_CNT;
    const int *sp, *dp;
    switch (set) {
        case 0:  sp = s0; dp = d0; break;
        case 1:  sp = s1; dp = d1; break;
        case 2:  sp = s2; dp = d2; break;
        default: sp = s3; dp = d3; break;
    }
    int gidx = seg_base(set) + dp[e];
    int pos = atomicAdd(cursor + gidx, 1);
    elist[rowptr[gidx] + pos] = sp[e];
}

// ---------------------------------------------------------------------------
// fused gather (bf16 proj in) -> fp8 messages
// ---------------------------------------------------------------------------
__global__ void gather_msgs(const bf* __restrict__ proj_ip,
                            const bf* __restrict__ proj_pp,
                            const bf* __restrict__ proj_fl,
                            const int* __restrict__ rowptr,
                            const int* __restrict__ elist,
                            const float* __restrict__ b_ip,
                            const float* __restrict__ b_fl,
                            uint8_t* __restrict__ mq)
{
    int w = (blockIdx.x * blockDim.x + threadIdx.x) >> 5;
    int lane = threadIdx.x & 31;
    if (w >= N_NODES) return;
    int rp = rowptr[w], re = rowptr[w + 1];
    int deg = re - rp;
    int j = lane * 4;
    float v0 = 0.f, v1 = 0.f, v2 = 0.f, v3 = 0.f;

    if (deg > 0) {
        const bf* P; int ld, po;
        const bf* pd; int pld, ppo, local;
        const float* bs;
        if (w < G_PPFL)      { local = w;           P = proj_pp; ld = 512; po = 0;   pd = proj_ip; pld = 256; ppo = 128; bs = b_ip; }
        else if (w < G_FL)   { local = w - G_PPFL;  P = proj_fl; ld = 256; po = 0;   pd = proj_pp; pld = 512; ppo = 384; bs = b_fl; }
        else if (w < G_PPIP) { local = w - G_FL;    P = proj_pp; ld = 512; po = 256; pd = proj_fl; pld = 256; ppo = 128; bs = b_fl; }
        else                 { local = w - G_PPIP;  P = proj_ip; ld = 256; po = 0;   pd = proj_pp; pld = 512; ppo = 128; bs = b_ip; }

        for (int base = 0; base < deg; base += 32) {
            int eid = (rp + base + lane < re) ? elist[rp + base + lane] : 0;
            int lim = deg - base; if (lim > 32) lim = 32;
            for (int k = 0; k < lim; ++k) {
                int src = __shfl_sync(0xffffffff, eid, k);
                const __nv_bfloat162* pr = (const __nv_bfloat162*)(P + (size_t)src * ld + po + j);
                float2 a = __bfloat1622float2(pr[0]);
                float2 b = __bfloat1622float2(pr[1]);
                v0 += a.x; v1 += a.y; v2 += b.x; v3 += b.y;
            }
        }
        float rc = 1.f / (float)deg;
        const __nv_bfloat162* pp2 = (const __nv_bfloat162*)(pd + (size_t)local * pld + ppo + j);
        float2 pa = __bfloat1622float2(pp2[0]);
        float2 pb = __bfloat1622float2(pp2[1]);
        v0 = v0 * rc + pa.x + bs[j];
        v1 = v1 * rc + pa.y + bs[j + 1];
        v2 = v2 * rc + pb.x + bs[j + 2];
        v3 = v3 * rc + pb.y + bs[j + 3];
    }
    uint32_t pk = (uint32_t)pk2(v0, v1) | ((uint32_t)pk2(v2, v3) << 16);
    *(uint32_t*)(mq + (size_t)w * H + j) = pk;
}

// ---------------------------------------------------------------------------
// GRU elementwise (4-wide, MUFU transcendentals):
// gates layout [rz(256) | gin(128) | ghn(128)] per row
// ---------------------------------------------------------------------------
__global__ void gru_elem(const bf* __restrict__ gmat,
                         bf* __restrict__ hb, uint8_t* __restrict__ hq, int Nn)
{
    int i = blockIdx.x * blockDim.x + threadIdx.x;
    if (i >= Nn * 32) return;
    int n = i >> 5, j = (i & 31) * 4;
    const bf* gr = gmat + (size_t)n * 512;

    float2 rA = __bfloat1622float2(*(const __nv_bfloat162*)(gr + j));
    float2 rB = __bfloat1622float2(*(const __nv_bfloat162*)(gr + j + 2));
    float2 zA = __bfloat1622float2(*(const __nv_bfloat162*)(gr + 128 + j));
    float2 zB = __bfloat1622float2(*(const __nv_bfloat162*)(gr + 128 + j + 2));
    float2 iA = __bfloat1622float2(*(const __nv_bfloat162*)(gr + 256 + j));
    float2 iB = __bfloat1622float2(*(const __nv_bfloat162*)(gr + 256 + j + 2));
    float2 hA = __bfloat1622float2(*(const __nv_bfloat162*)(gr + 384 + j));
    float2 hB = __bfloat1622float2(*(const __nv_bfloat162*)(gr + 384 + j + 2));
    float2 vA = __bfloat1622float2(*(const __nv_bfloat162*)(hb + (size_t)n * H + j));
    float2 vB = __bfloat1622float2(*(const __nv_bfloat162*)(hb + (size_t)n * H + j + 2));

    float o0, o1, o2, o3;
    {
        float r = fsig(rA.x), z = fsig(zA.x);
        float nn = ftanh(iA.x + r * hA.x);
        o0 = (1.f - z) * nn + z * vA.x;
    }
    {
        float r = fsig(rA.y), z = fsig(zA.y);
        float nn = ftanh(iA.y + r * hA.y);
        o1 = (1.f - z) * nn + z * vA.y;
    }
    {
        float r = fsig(rB.x), z = fsig(zB.x);
        float nn = ftanh(iB.x + r * hB.x);
        o2 = (1.f - z) * nn + z * vB.x;
    }
    {
        float r = fsig(rB.y), z = fsig(zB.y);
        float nn = ftanh(iB.y + r * hB.y);
        o3 = (1.f - z) * nn + z * vB.y;
    }

    *(__nv_bfloat162*)(hb + (size_t)n * H + j)     = __floats2bfloat162_rn(o0, o1);
    *(__nv_bfloat162*)(hb + (size_t)n * H + j + 2) = __floats2bfloat162_rn(o2, o3);
    *(uint32_t*)(hq + (size_t)n * H + j) =
        (uint32_t)pk2(o0, o1) | ((uint32_t)pk2(o2, o3) << 16);
}

// ---------------------------------------------------------------------------
// init
// ---------------------------------------------------------------------------
__global__ void prep_weights(const float* __restrict__ wmi, const float* __restrict__ wmf,
                             const float* __restrict__ wii, const float* __restrict__ whi,
                             const float* __restrict__ wif, const float* __restrict__ whf,
                             const float* __restrict__ w1,  const float* __restrict__ w2,
                             const float* __restrict__ bii, const float* __restrict__ bhi,
                             const float* __restrict__ bif, const float* __restrict__ bhf,
                             bf* __restrict__ wb, uint8_t* __restrict__ wq,
                             float* __restrict__ bias,
                             int* __restrict__ cnt, int* __restrict__ cursor)
{
    int t = blockIdx.x * blockDim.x + threadIdx.x;
    if (t < N_NODES) { cnt[t] = 0; cursor[t] = 0; }
    if (t < 256) bias[t] = bii[t] + bhi[t];
    else if (t < 512) bias[t] = bif[t - 256] + bhf[t - 256];
    if (t >= (int)(WB_TOTAL / 2)) return;
    float v[2];
#pragma unroll
    for (int q = 0; q < 2; ++q) {
        int i = 2 * t + q;
        if (i < 65536) {
            const float* s = (i < 32768) ? wmi : wmf;
            int o = i & 32767;
            int n = o >> 7, k = o & 127;
            v[q] = (n < 128) ? s[n * 256 + k] : s[(n - 128) * 256 + 128 + k];
        } else if (i < 114688) v[q] = wii[i - 65536];
        else if (i < 163840)   v[q] = whi[i - 114688];
        else if (i < 212992)   v[q] = wif[i - 163840];
        else if (i < 262144)   v[q] = whf[i - 212992];
        else if (i < 278528)   v[q] = w1[i - 262144];
        else                   v[q] = w2[i - 278528];
    }
    *(__nv_bfloat162*)(wb + 2 * t) = __floats2bfloat162_rn(v[0], v[1]);
    *(uint16_t*)(wq + 2 * t) = pk2(v[0], v[1]);
}

__global__ void init_states(const float* __restrict__ x_ip,
                            const float* __restrict__ x_pp,
                            const float* __restrict__ x_fl,
                            bf* __restrict__ hb, uint8_t* __restrict__ hq)
{
    int t = blockIdx.x * blockDim.x + threadIdx.x;
    if (t >= HB_ROWS * 64) return;
    int n = t >> 6, j = (t & 63) * 2;
    float v0, v1;
    if (n < HB_PP) {
        v0 = x_ip[(size_t)n * H + j]; v1 = x_ip[(size_t)n * H + j + 1];
    } else if (n < HB_FL) {
        const float* r = x_pp + (size_t)(n - HB_PP) * H;
        v0 = r[j]; v1 = r[j + 1];
    } else {
        const float* r = x_fl + (size_t)(n - HB_FL) * IN_C;
        v0 = (j < IN_C) ? r[j] : 0.f;
        v1 = (j + 1 < IN_C) ? r[j + 1] : 0.f;
    }
    *(__nv_bfloat162*)(hb + (size_t)n * H + j) = __floats2bfloat162_rn(v0, v1);
    *(uint16_t*)(hq + (size_t)n * H + j) = pk2(v0, v1);
}

__global__ void readout_final(const bf* __restrict__ r2,
                              const float* __restrict__ W3,
                              const float* __restrict__ b3,
                              float* __restrict__ out)
{
    int n = blockIdx.x * blockDim.x + threadIdx.x;
    if (n >= N_FL) return;
    float l0 = b3[0], l1 = b3[1];
    const bf* r = r2 + (size_t)n * 64;
#pragma unroll
    for (int k = 0; k < 64; ++k) {
        float rv = __bfloat162float(r[k]);
        l0 = fmaf(rv, W3[k], l0);
        l1 = fmaf(rv, W3[64 + k], l1);
    }
    out[2 * n + 0] = fsig(l0 - l1);
    out[2 * n + 1] = fsig(l1 - l0);
}

// ---------------------------------------------------------------------------
// Host orchestration
// ---------------------------------------------------------------------------
static constexpr int GSMEM = 4 * 5120 * 2 * 2;  // 81920 B (bf16 kernel)

struct JobSpec {
    const void* A; const void* W; const void* A2; const void* W2;
    const float* bias; bf* C;
    int M, N, ldc, cofs, relu;
};

static void fill_jobs(Jobs& js, const JobSpec* sp, int nj, int bnw, int& tiles)
{
    js.njobs = nj;
    tiles = 0;
    for (int k = 0; k < nj; ++k) {
        Job& J = js.j[k];
        J.A = sp[k].A; J.W = sp[k].W; J.A2 = sp[k].A2; J.W2 = sp[k].W2;
        J.bias = sp[k].bias; J.C = sp[k].C;
        J.M = sp[k].M; J.N = sp[k].N; J.ldc = sp[k].ldc; J.cofs = sp[k].cofs;
        J.relu = sp[k].relu;
        J.nx = (sp[k].N + bnw - 1) / bnw;
        J.tile_start = tiles;
        tiles += J.nx * ((sp[k].M + 127) / 128);
    }
    for (int k = nj; k < 6; ++k) js.j[k] = js.j[nj - 1];
}

static inline void launch_jobs8(const JobSpec* sp, int nj)
{
    Jobs js; int tiles;
    fill_jobs(js, sp, nj, 64, tiles);
    bgemm8<<<tiles, 256>>>(js);
}

static inline void launch_jobs16(const JobSpec* sp, int nj)
{
    static int attr_set = 0;
    if (!attr_set) {
        cudaFuncSetAttribute(bgemm, cudaFuncAttributeMaxDynamicSharedMemorySize, GSMEM);
        attr_set = 1;
    }
    Jobs js; int tiles;
    fill_jobs(js, sp, nj, 128, tiles);
    bgemm<<<tiles, 256, GSMEM>>>(js);
}

extern "C" void kernel_launch(void* const* d_in, const int* in_sizes, int n_in,
                              void* d_out, int out_size)
{
    (void)in_sizes; (void)n_in; (void)out_size;

    const float* x_ip     = (const float*)d_in[0];
    const float* x_pp     = (const float*)d_in[1];
    const float* x_fl     = (const float*)d_in[2];
    const float* W_msg_ip = (const float*)d_in[3];
    const float* b_msg_ip = (const float*)d_in[4];
    const float* W_msg_fl = (const float*)d_in[5];
    const float* b_msg_fl = (const float*)d_in[6];
    const float* w_ih_ip  = (const float*)d_in[7];
    const float* w_hh_ip  = (const float*)d_in[8];
    const float* b_ih_ip  = (const float*)d_in[9];
    const float* b_hh_ip  = (const float*)d_in[10];
    const float* w_ih_fl  = (const float*)d_in[11];
    const float* w_hh_fl  = (const float*)d_in[12];
    const float* b_ih_fl  = (const float*)d_in[13];
    const float* b_hh_fl  = (const float*)d_in[14];
    const float* W1       = (const float*)d_in[15];
    const float* b1       = (const float*)d_in[16];
    const float* W2       = (const float*)d_in[17];
    const float* b2       = (const float*)d_in[18];
    const float* W3       = (const float*)d_in[19];
    const float* b3       = (const float*)d_in[20];
    const int* src_ip2pp  = (const int*)d_in[21];
    const int* dst_ip2pp  = (const int*)d_in[22];
    const int* src_pp2ip  = (const int*)d_in[23];
    const int* dst_pp2ip  = (const int*)d_in[24];
    const int* src_pp2fl  = (const int*)d_in[25];
    const int* dst_pp2fl  = (const int*)d_in[26];
    const int* src_fl2pp  = (const int*)d_in[27];
    const int* dst_fl2pp  = (const int*)d_in[28];
    float* out = (float*)d_out;

    bf* bb;       cudaGetSymbolAddress((void**)&bb, d_b16);
    uint8_t* qb;  cudaGetSymbolAddress((void**)&qb, d_fp8);
    float* biasb; cudaGetSymbolAddress((void**)&biasb, d_bias);
    int* cnt;     cudaGetSymbolAddress((void**)&cnt, d_cnt);
    int* cursor;  cudaGetSymbolAddress((void**)&cursor, d_cursor);
    int* rowptr;  cudaGetSymbolAddress((void**)&rowptr, d_rowptr);
    int* elist;   cudaGetSymbolAddress((void**)&elist, d_elist);
    int* bsum;    cudaGetSymbolAddress((void**)&bsum, d_bsum);
    int* boff;    cudaGetSymbolAddress((void**)&boff, d_boff);

    bf* hb      = bb + B_HB;
    bf* hb_pp   = hb + (size_t)HB_PP * H;
    bf* hb_fl   = hb + (size_t)HB_FL * H;
    bf* proj_ip = bb + B_PROJ_IP;
    bf* proj_pp = bb + B_PROJ_PP;
    bf* proj_fl = bb + B_PROJ_FL;
    bf* gmat    = bb + B_G;
    bf* gmat2   = bb + B_G2;
    bf* r1      = bb + B_R1;
    bf* r2      = bb + B_R2;
    bf* wb      = bb + B_WB;

    uint8_t* hq    = qb + Q_HQ;
    uint8_t* hq_pp = hq + (size_t)HB_PP * H;
    uint8_t* hq_fl = hq + (size_t)HB_FL * H;
    uint8_t* mq    = qb + Q_MQ;
    uint8_t* wq    = qb + Q_WQ;

    bf* wb_w1 = wb + WB_W1;
    bf* wb_w2 = wb + WB_W2;
    uint8_t* wq_msg   = wq + WB_MSG;
    uint8_t* wq_ih_ip = wq + WB_IH_IP;
    uint8_t* wq_hh_ip = wq + WB_HH_IP;
    uint8_t* wq_ih_fl = wq + WB_IH_FL;
    uint8_t* wq_hh_fl = wq + WB_HH_FL;

    // --- init; launch #4 = first fp8 bgemm (profiled by ncu) ---
    {
        int g = (N_NODES > (int)(WB_TOTAL / 2)) ? N_NODES : (int)(WB_TOTAL / 2);
        prep_weights<<<(g + 255) / 256, 256>>>(
            W_msg_ip, W_msg_fl, w_ih_ip, w_hh_ip, w_ih_fl, w_hh_fl, W1, W2,
            b_ih_ip, b_hh_ip, b_ih_fl, b_hh_fl,
            wb, wq, biasb, cnt, cursor);
    }
    init_states<<<(HB_ROWS * 64 + 255) / 256, 256>>>(x_ip, x_pp, x_fl, hb, hq);
    edge_hist<<<(4 * E_CNT + 255) / 256, 256>>>(dst_ip2pp, dst_pp2ip, dst_pp2fl, dst_fl2pp, cnt);

    // projections for iter 0 (bf16 out)
    {
        JobSpec sp[3] = {
            { hq,    wq_msg,             nullptr, nullptr, nullptr, proj_ip, N_IP, 256, 256, 0, 0 },
            { hq_fl, wq_msg + 256 * 128, nullptr, nullptr, nullptr, proj_fl, N_FL, 256, 256, 0, 0 },
            { hq_pp, wq_msg,             nullptr, nullptr, nullptr, proj_pp, N_PP, 512, 512, 0, 0 },
        };
        launch_jobs8(sp, 3);
    }

    scan_part<<<SC_NB, SC_T>>>(cnt, bsum);
    scan_top<<<1, 128>>>(bsum, boff);
    scan_final<<<SC_NB, SC_T>>>(cnt, boff, rowptr);
    edge_fill<<<(4 * E_CNT + 255) / 256, 256>>>(src_ip2pp, dst_ip2pp, src_pp2ip, dst_pp2ip,
                                                src_pp2fl, dst_pp2fl, src_fl2pp, dst_fl2pp,
                                                rowptr, cursor, elist);

    for (int it = 0; it < N_ITER; ++it) {
        // 1. gather -> fp8 messages
        gather_msgs<<<(N_NODES * 32 + 255) / 256, 256>>>(proj_ip, proj_pp, proj_fl,
                                                         rowptr, elist, b_msg_ip, b_msg_fl, mq);

        // 2. GRU phase A: fused rz (K=256 split) + separate n-gate halves; 6 jobs
        {
            JobSpec sp[6] = {
                { mq,                    wq_ih_ip,             hq,    wq_hh_ip,             biasb,          gmat,                      70000, 256, 512, 0,   0 },
                { mq,                    wq_ih_ip + 256 * 128, nullptr, nullptr,            b_ih_ip + 256,  gmat,                      70000, 128, 512, 256, 0 },
                { hq,                    wq_hh_ip + 256 * 128, nullptr, nullptr,            b_hh_ip + 256,  gmat,                      70000, 128, 512, 384, 0 },
                { mq + (size_t)G_FL * H, wq_ih_fl,             hq_fl, wq_hh_fl,             biasb + 256,    gmat + (size_t)70000*512,  N_FL,  256, 512, 0,   0 },
                { mq + (size_t)G_FL * H, wq_ih_fl + 256 * 128, nullptr, nullptr,            b_ih_fl + 256,  gmat + (size_t)70000*512,  N_FL,  128, 512, 256, 0 },
                { hq_fl,                 wq_hh_fl + 256 * 128, nullptr, nullptr,            b_hh_fl + 256,  gmat + (size_t)70000*512,  N_FL,  128, 512, 384, 0 },
            };
            launch_jobs8(sp, 6);
        }
        gru_elem<<<(HB_ROWS * 32 + 255) / 256, 256>>>(gmat, hb, hq, HB_ROWS);

        // 3. GRU phase B: pp(ip2pp) gates (needs updated h_pp) + next-iter ip/fl projections
        {
            JobSpec sp[5] = {
                { mq + (size_t)G_PPIP * H, wq_ih_ip,             hq_pp, wq_hh_ip,  biasb,         gmat2,   N_PP, 256, 512, 0,   0 },
                { mq + (size_t)G_PPIP * H, wq_ih_ip + 256 * 128, nullptr, nullptr, b_ih_ip + 256, gmat2,   N_PP, 128, 512, 256, 0 },
                { hq_pp,                   wq_hh_ip + 256 * 128, nullptr, nullptr, b_hh_ip + 256, gmat2,   N_PP, 128, 512, 384, 0 },
                { hq,                      wq_msg,               nullptr, nullptr, nullptr,       proj_ip, N_IP, 256, 256, 0,   0 },
                { hq_fl,                   wq_msg + 256 * 128,   nullptr, nullptr, nullptr,       proj_fl, N_FL, 256, 256, 0,   0 },
            };
            launch_jobs8(sp, (it < N_ITER - 1) ? 5 : 3);
        }
        gru_elem<<<(N_PP * 32 + 255) / 256, 256>>>(gmat2, hb_pp, hq_pp, N_PP);

        // 4. proj_pp for next iter (needs updated h_pp)
        if (it < N_ITER - 1) {
            JobSpec sp[1] = {
                { hq_pp, wq_msg, nullptr, nullptr, nullptr, proj_pp, N_PP, 512, 512, 0, 0 },
            };
            launch_jobs8(sp, 1);
        }
    }

    // readout (bf16)
    {
        JobSpec sp1[1] = { { hb_fl, wb_w1, nullptr, nullptr, b1, r1, N_FL, 128, 128, 0, 1 } };
        launch_jobs16(sp1, 1);
        JobSpec sp2[1] = { { r1, wb_w2, nullptr, nullptr, b2, r2, N_FL, 64, 64, 0, 1 } };
        launch_jobs16(sp2, 1);
    }
    readout_final<<<(N_FL + 127) / 128, 128>>>(r2, W3, b3, out);
}